// round 16
// baseline (speedup 1.0000x reference)
#include <cuda_runtime.h>
#include <cuda_bf16.h>
#include <cuda_fp16.h>
#include <math.h>
#include <stdint.h>

// ---------------- problem constants ----------------
#define Bsz    4
#define Cdim   256
#define Hh     128
#define Wd     128
#define Np     (Hh*Wd)        // 16384
#define CH3    (3*Cdim)       // 768
#define HID    680
#define HID2   1360
#define NHEADS 8
#define HD     32
#define SPLITS 128
#define CHUNK  (Np/SPLITS)    // 128

#define KPAD_G 704
#define MPAD_PIN 1408

// static power-of-2 scales for fp16 range safety (exactly inverted in epilogue)
#define SC_AV   16.f
#define SC_GATE 512.f

// ---------------- scratch (device globals; no runtime alloc) ----------------
__device__ __align__(16) __nv_bfloat16 g_qkv [(size_t)Bsz*CH3 *Np];
__device__ __align__(16) __nv_bfloat16 g_qkv2[(size_t)Bsz*CH3 *Np];
__device__ float g_ssq  [2][Bsz][Cdim][2];   // [q/k][b][c][half] partial sumsq
__device__ float g_spart[(size_t)Bsz*NHEADS*SPLITS*HD*HD];
__device__ float g_attn [Bsz*NHEADS*HD*HD];
__device__ float g_x1   [(size_t)Bsz*Cdim*Np];
__device__ __align__(16) __nv_bfloat16 g_pin [(size_t)Bsz*HID2*Np];
__device__ __align__(16) __half g_gate[(size_t)Bsz*KPAD_G*Np];   // fp16, [b][c(pad 704)][n], x SC_GATE

// fp16 operand buffer (X): [c][n] for LN outputs, [n][256] for av output
__device__ __align__(16) __half g_xh[(size_t)Bsz*Np*KPAD_G];
// weights: qkv(768*256) | po(256*256) | pin(1408*256) | pout(256*704)
#define WOFF_QKV  0
#define WOFF_PO   (768*256)
#define WOFF_PIN  (WOFF_PO + 256*256)
#define WOFF_POUT (WOFF_PIN + 1408*256)
#define WTOT      (WOFF_POUT + 256*704)
__device__ __align__(16) __half g_wh[WTOT];

// ---------------- PTX helpers ----------------
__device__ __forceinline__ uint32_t smem_u32(const void* p) {
    uint32_t a;
    asm("{ .reg .u64 t; cvta.to.shared.u64 t, %1; cvt.u32.u64 %0, t; }" : "=r"(a) : "l"(p));
    return a;
}
#define CP_ASYNC16(dst, src) \
    asm volatile("cp.async.cg.shared.global [%0], [%1], 16;" :: "r"(dst), "l"(src) : "memory")
#define CP_COMMIT() asm volatile("cp.async.commit_group;" ::: "memory")
#define CP_WAIT(n)  asm volatile("cp.async.wait_group %0;" :: "n"(n) : "memory")

__device__ __forceinline__ void ldsm4(uint32_t* r, uint32_t addr) {
    asm volatile("ldmatrix.sync.aligned.m8n8.x4.shared.b16 {%0,%1,%2,%3}, [%4];"
                 : "=r"(r[0]), "=r"(r[1]), "=r"(r[2]), "=r"(r[3]) : "r"(addr));
}
__device__ __forceinline__ void ldsm4t(uint32_t* r, uint32_t addr) {
    asm volatile("ldmatrix.sync.aligned.m8n8.x4.trans.shared.b16 {%0,%1,%2,%3}, [%4];"
                 : "=r"(r[0]), "=r"(r[1]), "=r"(r[2]), "=r"(r[3]) : "r"(addr));
}
// fp16 MMA with fp16 accumulators (2 packed regs)
__device__ __forceinline__ void mma16816h(uint32_t* c, const uint32_t* a, const uint32_t* b) {
    asm volatile(
        "mma.sync.aligned.m16n8k16.row.col.f16.f16.f16.f16 "
        "{%0,%1}, {%2,%3,%4,%5}, {%6,%7}, {%0,%1};"
        : "+r"(c[0]), "+r"(c[1])
        : "r"(a[0]), "r"(a[1]), "r"(a[2]), "r"(a[3]), "r"(b[0]), "r"(b[1]));
}
__device__ __forceinline__ uint32_t packbf2(float a, float b) {
    __nv_bfloat162 h = __floats2bfloat162_rn(a, b);
    return *(uint32_t*)&h;
}
__device__ __forceinline__ uint32_t packh2(float a, float b) {
    __half2 h = __floats2half2_rn(a, b);
    return *(uint32_t*)&h;
}
__device__ __forceinline__ void unpack8(const uint4 v, float* r) {
    float2 f;
    f = __bfloat1622float2(*(const __nv_bfloat162*)&v.x); r[0] = f.x; r[1] = f.y;
    f = __bfloat1622float2(*(const __nv_bfloat162*)&v.y); r[2] = f.x; r[3] = f.y;
    f = __bfloat1622float2(*(const __nv_bfloat162*)&v.z); r[4] = f.x; r[5] = f.y;
    f = __bfloat1622float2(*(const __nv_bfloat162*)&v.w); r[6] = f.x; r[7] = f.y;
}
// fp32 variant: r[0..9] = pixels x0-1 .. x0+8 from fp32 smem row
__device__ __forceinline__ void load_row10f(float* r, const float* rowp, int x0) {
    float4 a = *(const float4*)(rowp + x0);
    float4 b2 = *(const float4*)(rowp + x0 + 4);
    r[1] = a.x; r[2] = a.y; r[3] = a.z; r[4] = a.w;
    r[5] = b2.x; r[6] = b2.y; r[7] = b2.z; r[8] = b2.w;
    r[0] = (x0 > 0)   ? rowp[x0 - 1] : 0.f;
    r[9] = (x0 < 120) ? rowp[x0 + 8] : 0.f;
}
__device__ __forceinline__ void load_row10(float* r, const __nv_bfloat16* t,
                                           int row, int x0, bool valid) {
    if (!valid) {
        #pragma unroll
        for (int i = 0; i < 10; i++) r[i] = 0.f;
        return;
    }
    const __nv_bfloat16* p = t + row * 128;
    uint4 v = *(const uint4*)(p + x0);
    unpack8(v, r + 1);
    r[0] = (x0 > 0)   ? __bfloat162float(p[x0 - 1]) : 0.f;
    r[9] = (x0 < 120) ? __bfloat162float(p[x0 + 8]) : 0.f;
}

// ================= mma.sync GEMM fp16/fp16-accum, 128x256 block, warp tile 64x64 =================
#define TARR_B    10240          // W tile: 128 rows x 80 B
#define XT_ROW    528            // trans X row: 512 B + 16 pad
#define XNT_ROW   80
#define STAGE_T   (TARR_B + 32*XT_ROW)    // 27136
#define STAGE_NT  (TARR_B + 256*XNT_ROW)  // 30720
#define GEMM_SMEM (3*STAGE_NT)            // 92160

template<bool B_TRANS>
__device__ __forceinline__ void gemm_issue_tile(
    uint32_t st, int tid, const __half* Wh, const __half* Xh_b,
    int rowBase, int Kpad, int k0)
{
    #pragma unroll
    for (int c = tid; c < 512; c += 256) {      // W: 128 rows x 64 B
        int r = c >> 2, cc = c & 3;
        CP_ASYNC16(st + r * 80 + cc * 16,
                   Wh + (size_t)(rowBase + r) * Kpad + k0 + cc * 8);
    }
    if (B_TRANS) {
        #pragma unroll
        for (int c = tid; c < 1024; c += 256) { // X: 32 k-rows x 512 B
            int r = c >> 5, cc = c & 31;
            CP_ASYNC16(st + TARR_B + r * XT_ROW + cc * 16,
                       Xh_b + (size_t)(k0 + r) * Np + cc * 8);
        }
    } else {
        #pragma unroll
        for (int c = tid; c < 1024; c += 256) { // X: 256 n-rows x 64 B
            int r = c >> 2, cc = c & 3;
            CP_ASYNC16(st + TARR_B + r * XNT_ROW + cc * 16,
                       Xh_b + (size_t)r * Kpad + k0 + cc * 8);
        }
    }
    CP_COMMIT();
}

template<bool OUT_BF16, bool B_TRANS>
__global__ __launch_bounds__(256) void gemm_mma_kernel(
    const __half* __restrict__ Wh,
    const __half* __restrict__ Xh,
    const float* __restrict__ bias, const float* __restrict__ res,
    void* __restrict__ outp, int M, int Kpad, float isc)
{
    extern __shared__ char smem[];
    const uint32_t sb = smem_u32(smem);
    const int tid = threadIdx.x, lane = tid & 31, wid = tid >> 5;
    const int warpM = wid & 1, warpN = wid >> 1;
    const int rowBase = blockIdx.y * 128, colBase = blockIdx.x * 256, b = blockIdx.z;
    const uint32_t stageB = B_TRANS ? STAGE_T : STAGE_NT;

    const __half* Xh_b = B_TRANS
        ? (Xh + (size_t)b * Kpad * Np + colBase)
        : (Xh + ((size_t)b * Np + colBase) * Kpad);

    uint32_t acc[4][8][2];
    #pragma unroll
    for (int i = 0; i < 4; i++)
        #pragma unroll
        for (int j = 0; j < 8; j++) { acc[i][j][0] = 0u; acc[i][j][1] = 0u; }

    const int nk = Kpad >> 5;
    gemm_issue_tile<B_TRANS>(sb,          tid, Wh, Xh_b, rowBase, Kpad, 0);
    gemm_issue_tile<B_TRANS>(sb + stageB, tid, Wh, Xh_b, rowBase, Kpad, 32);

    for (int i = 0; i < nk; i++) {
        if (i + 1 < nk) CP_WAIT(1); else CP_WAIT(0);
        __syncthreads();
        if (i + 2 < nk)
            gemm_issue_tile<B_TRANS>(sb + ((i + 2) % 3) * stageB, tid, Wh, Xh_b,
                                     rowBase, Kpad, (i + 2) << 5);

        const uint32_t st = sb + (i % 3) * stageB;
        #pragma unroll
        for (int kk = 0; kk < 2; kk++) {
            uint32_t aA[4][4], bB[8][2];
            const int arow = lane & 15, ahalf = lane >> 4;
            #pragma unroll
            for (int mf = 0; mf < 4; mf++) {
                uint32_t ad = st + (uint32_t)(warpM * 64 + mf * 16 + arow) * 80
                              + kk * 32 + ahalf * 16;
                ldsm4(aA[mf], ad);
            }
            if (B_TRANS) {
                #pragma unroll
                for (int g2 = 0; g2 < 4; g2++) {
                    int kl = lane & 15;
                    int noff = warpN * 64 + g2 * 16 + ((lane & 16) ? 8 : 0);
                    uint32_t bd = st + TARR_B + (uint32_t)(kk * 16 + kl) * XT_ROW + noff * 2;
                    uint32_t t[4];
                    ldsm4t(t, bd);
                    bB[g2*2][0] = t[0]; bB[g2*2][1] = t[1];
                    bB[g2*2+1][0] = t[2]; bB[g2*2+1][1] = t[3];
                }
            } else {
                #pragma unroll
                for (int nfp = 0; nfp < 4; nfp++) {
                    int nrow = warpN * 64 + nfp * 16 + ((lane >> 4) * 8 + (lane & 7));
                    int kb = (lane >> 3) & 1;
                    uint32_t bd = st + TARR_B + (uint32_t)nrow * XNT_ROW + kk * 32 + kb * 16;
                    uint32_t t[4];
                    ldsm4(t, bd);
                    bB[nfp*2][0] = t[0]; bB[nfp*2][1] = t[1];
                    bB[nfp*2+1][0] = t[2]; bB[nfp*2+1][1] = t[3];
                }
            }
            #pragma unroll
            for (int mf = 0; mf < 4; mf++)
                #pragma unroll
                for (int nf = 0; nf < 8; nf++)
                    mma16816h(acc[mf][nf], aA[mf], bB[nf]);
        }
    }

    #pragma unroll
    for (int mf = 0; mf < 4; mf++) {
        int r0 = rowBase + warpM * 64 + mf * 16 + (lane >> 2);
        int r1 = r0 + 8;
        #pragma unroll
        for (int nf = 0; nf < 8; nf++) {
            int c0 = colBase + warpN * 64 + nf * 8 + 2 * (lane & 3);
            float2 lo = __half22float2(*(const __half2*)&acc[mf][nf][0]);
            float2 hi = __half22float2(*(const __half2*)&acc[mf][nf][1]);
            if (r0 < M) {
                float bb = __ldg(bias + r0);
                size_t go = ((size_t)b * M + r0) * Np + c0;
                float v0 = lo.x * isc + bb, v1 = lo.y * isc + bb;
                if (OUT_BF16) {
                    *(uint32_t*)((__nv_bfloat16*)outp + go) = packbf2(v0, v1);
                } else {
                    if (res) { float2 rr = *(const float2*)(res + go); v0 += rr.x; v1 += rr.y; }
                    *(float2*)((float*)outp + go) = make_float2(v0, v1);
                }
            }
            if (r1 < M) {
                float bb = __ldg(bias + r1);
                size_t go = ((size_t)b * M + r1) * Np + c0;
                float v0 = hi.x * isc + bb, v1 = hi.y * isc + bb;
                if (OUT_BF16) {
                    *(uint32_t*)((__nv_bfloat16*)outp + go) = packbf2(v0, v1);
                } else {
                    if (res) { float2 rr = *(const float2*)(res + go); v0 += rr.x; v1 += rr.y; }
                    *(float2*)((float*)outp + go) = make_float2(v0, v1);
                }
            }
        }
    }
}

// ---------------- single-pass LayerNorm -> fp16 [c][n] (coalesced) ----------------
__global__ __launch_bounds__(256) void ln_fp16_kernel(
    const float* __restrict__ in, const float* __restrict__ w,
    const float* __restrict__ bs, __half* __restrict__ xc)
{
    __shared__ float red_s[8][33];
    __shared__ float red_q[8][33];
    __shared__ float s_mu[32], s_rs[32];
    int b = blockIdx.y;
    int n0 = blockIdx.x * 32;
    int wci = threadIdx.x >> 5, lane = threadIdx.x & 31;
    int n = n0 + lane;
    const float* p = in + (size_t)b * Cdim * Np + (size_t)(wci * 32) * Np + n;
    float v[32];
    float s = 0.f, q = 0.f;
    #pragma unroll
    for (int j = 0; j < 32; j++) {
        v[j] = p[(size_t)j * Np];
        s += v[j]; q += v[j] * v[j];
    }
    red_s[wci][lane] = s;
    red_q[wci][lane] = q;
    __syncthreads();
    if (threadIdx.x < 32) {
        float ts = 0.f, tq = 0.f;
        #pragma unroll
        for (int k2 = 0; k2 < 8; k2++) { ts += red_s[k2][threadIdx.x]; tq += red_q[k2][threadIdx.x]; }
        float mu = ts * (1.f / Cdim);
        float var = fmaxf(tq * (1.f / Cdim) - mu * mu, 0.f);
        s_mu[threadIdx.x] = mu;
        s_rs[threadIdx.x] = rsqrtf(var + 1e-5f);
    }
    __syncthreads();
    float mu = s_mu[lane], rs = s_rs[lane];
    int c0 = wci * 32;
    __half* o = xc + ((size_t)b * Cdim + c0) * Np + n;
    #pragma unroll
    for (int j = 0; j < 32; j++) {
        float y = (v[j] - mu) * rs * __ldg(w + c0 + j) + __ldg(bs + c0 + j);
        o[(size_t)j * Np] = __float2half(y);
    }
}

// ---------------- zero the 24 pad channels of g_gate ----------------
__global__ void gatepad_kernel()
{
    size_t idx = (size_t)blockIdx.x * 256 + threadIdx.x;
    size_t per_b = (size_t)(KPAD_G - HID) * Np / 8;
    int b = (int)(idx / per_b);
    size_t l = (idx % per_b) * 8;
    *(uint4*)(g_gate + (size_t)b * KPAD_G * Np + (size_t)HID * Np + l) =
        make_uint4(0u, 0u, 0u, 0u);
}

// ---------------- combined weight fp16 convert ----------------
__global__ void wconv_all_kernel(
    const float* __restrict__ qkv_w, const float* __restrict__ po_w,
    const float* __restrict__ pin_w, const float* __restrict__ pout_w,
    __half* __restrict__ wh)
{
    int idx = blockIdx.x * 256 + threadIdx.x;
    if (idx >= WTOT) return;
    float v;
    if (idx < WOFF_PO) {
        v = qkv_w[idx];
    } else if (idx < WOFF_PIN) {
        v = po_w[idx - WOFF_PO];
    } else if (idx < WOFF_POUT) {
        int l = idx - WOFF_PIN;              // [1408][256]
        v = (l < 1360 * 256) ? pin_w[l] : 0.f;
    } else {
        int l = idx - WOFF_POUT;             // [256][704]
        int r = l / 704, k = l % 704;
        v = (k < 680) ? pout_w[r * 680 + k] : 0.f;
    }
    wh[idx] = __float2half(v);
}

// ---------------- fused depthwise 3x3 + q/k partial L2, fp32 tiles, 64-row halves ----------------
#define DWN_SMEM (66*128*4)   // 33792 B
__global__ __launch_bounds__(256) void dwnorm_kernel(
    const __nv_bfloat16* __restrict__ in, const float* __restrict__ w,
    const float* __restrict__ bias, __nv_bfloat16* __restrict__ out)
{
    extern __shared__ float tf[];   // 66 rows x 128 fp32
    int blk = blockIdx.x;
    int half = blk & 1;
    int c = (blk >> 1) % CH3;
    int b = blk / (2 * CH3);
    int h0 = half * 64;
    const int tid = threadIdx.x;

    const __nv_bfloat16* ip = in + ((size_t)b * CH3 + c) * Np;
    for (int i = tid; i < 66 * 16; i += 256) {
        int r = i >> 4, q = i & 15;
        int grow = h0 - 1 + r;
        float rr[8] = {0,0,0,0,0,0,0,0};
        if (grow >= 0 && grow < Hh) {
            uint4 v = *(const uint4*)(ip + grow * Wd + q * 8);
            unpack8(v, rr);
        }
        *(float4*)(tf + r * 128 + q * 8)     = make_float4(rr[0], rr[1], rr[2], rr[3]);
        *(float4*)(tf + r * 128 + q * 8 + 4) = make_float4(rr[4], rr[5], rr[6], rr[7]);
    }
    __syncthreads();

    float w00 = w[c*9+0], w01 = w[c*9+1], w02 = w[c*9+2];
    float w10 = w[c*9+3], w11 = w[c*9+4], w12 = w[c*9+5];
    float w20 = w[c*9+6], w21 = w[c*9+7], w22 = w[c*9+8];
    float bb = bias[c];
    __nv_bfloat16* op = out + ((size_t)b * CH3 + c) * Np + h0 * Wd;
    float ss = 0.f;

    #pragma unroll
    for (int it = 0; it < 4; it++) {
        int base = it * 2048 + tid * 8;
        int h = base >> 7, x0 = base & 127;
        float r0[10], r1[10], r2[10];
        load_row10f(r0, tf + h * 128,       x0);
        load_row10f(r1, tf + (h + 1) * 128, x0);
        load_row10f(r2, tf + (h + 2) * 128, x0);
        float o[8];
        #pragma unroll
        for (int i = 0; i < 8; i++) {
            float acc = bb;
            acc += w00 * r0[i] + w01 * r0[i+1] + w02 * r0[i+2];
            acc += w10 * r1[i] + w11 * r1[i+1] + w12 * r1[i+2];
            acc += w20 * r2[i] + w21 * r2[i+1] + w22 * r2[i+2];
            o[i] = acc;
            ss += acc * acc;
        }
        uint4 pk;
        pk.x = packbf2(o[0], o[1]);
        pk.y = packbf2(o[2], o[3]);
        pk.z = packbf2(o[4], o[5]);
        pk.w = packbf2(o[6], o[7]);
        *(uint4*)(op + base) = pk;
    }

    if (c < 2 * Cdim) {
        #pragma unroll
        for (int o2 = 16; o2 > 0; o2 >>= 1) ss += __shfl_xor_sync(0xffffffffu, ss, o2);
        __shared__ float red[8];
        int wid = tid >> 5;
        if ((tid & 31) == 0) red[wid] = ss;
        __syncthreads();
        if (tid == 0) {
            float s = 0.f;
            #pragma unroll
            for (int i = 0; i < 8; i++) s += red[i];
            g_ssq[c >> 8][b][c & 255][half] = s;
        }
    }
}

// ---------------- split-K partial S, 4x4 register tiles, vectorized smem ----------------
__global__ __launch_bounds__(256) void spart_kernel(const __nv_bfloat16* __restrict__ qkv2)
{
    __shared__ float qs[CHUNK][36];
    __shared__ float ks[CHUNK][36];
    int split = blockIdx.x, h = blockIdx.y, b = blockIdx.z;
    int n0 = split * CHUNK;
    int tid = threadIdx.x;
    for (int idx = tid; idx < HD * CHUNK; idx += 256) {
        int i = idx >> 7, nn = idx & 127;
        qs[nn][i] = __bfloat162float(qkv2[((size_t)b * CH3 + h * HD + i) * Np + n0 + nn]);
        ks[nn][i] = __bfloat162float(qkv2[((size_t)b * CH3 + Cdim + h * HD + i) * Np + n0 + nn]);
    }
    __syncthreads();

    const int g  = tid >> 6;
    const int i0 = (tid >> 3) & 7;
    const int j0 = tid & 7;
    float acc[4][4];
    #pragma unroll
    for (int a = 0; a < 4; a++)
        #pragma unroll
        for (int c2 = 0; c2 < 4; c2++) acc[a][c2] = 0.f;

    #pragma unroll 4
    for (int nn = g * 32; nn < g * 32 + 32; nn++) {
        float4 qv = *(const float4*)&qs[nn][i0 * 4];
        float4 kv = *(const float4*)&ks[nn][j0 * 4];
        acc[0][0] += qv.x*kv.x; acc[0][1] += qv.x*kv.y; acc[0][2] += qv.x*kv.z; acc[0][3] += qv.x*kv.w;
        acc[1][0] += qv.y*kv.x; acc[1][1] += qv.y*kv.y; acc[1][2] += qv.y*kv.z; acc[1][3] += qv.y*kv.w;
        acc[2][0] += qv.z*kv.x; acc[2][1] += qv.z*kv.y; acc[2][2] += qv.z*kv.z; acc[2][3] += qv.z*kv.w;
        acc[3][0] += qv.w*kv.x; acc[3][1] += qv.w*kv.y; acc[3][2] += qv.w*kv.z; acc[3][3] += qv.w*kv.w;
    }
    __syncthreads();
    float* red = &qs[0][0];
    #pragma unroll
    for (int x = 0; x < 16; x++) red[tid * 17 + x] = acc[x >> 2][x & 3];
    __syncthreads();
    if (tid < 64) {
        size_t base = (((size_t)(b * NHEADS + h)) * SPLITS + split) * (HD * HD);
        #pragma unroll
        for (int x = 0; x < 16; x++) {
            float s = red[tid * 17 + x] + red[(tid + 64) * 17 + x]
                    + red[(tid + 128) * 17 + x] + red[(tid + 192) * 17 + x];
            int i = i0 * 4 + (x >> 2), j = j0 * 4 + (x & 3);
            g_spart[base + i * HD + j] = s;
        }
    }
}

// ---------------- reduce partials + norms + softmax ----------------
__global__ __launch_bounds__(1024) void attn_reduce_kernel(const float* __restrict__ temp)
{
    int bh = blockIdx.x;
    int b = bh / NHEADS, h = bh % NHEADS;
    int tid = threadIdx.x;
    int i = tid >> 5, j = tid & 31;
    const float* p = g_spart + (size_t)bh * SPLITS * (HD * HD) + tid;
    float s = 0.f;
    #pragma unroll 4
    for (int sp = 0; sp < SPLITS; sp++) s += p[(size_t)sp * (HD * HD)];
    int ci = h * HD + i, cj = h * HD + j;
    float sqq = g_ssq[0][b][ci][0] + g_ssq[0][b][ci][1];
    float sqk = g_ssq[1][b][cj][0] + g_ssq[1][b][cj][1];
    float inv_i = 1.f / fmaxf(sqrtf(sqq), 1e-12f);
    float inv_j = 1.f / fmaxf(sqrtf(sqk), 1e-12f);
    s *= inv_i * inv_j * temp[h];
    float m = s;
    #pragma unroll
    for (int o = 16; o > 0; o >>= 1) m = fmaxf(m, __shfl_xor_sync(0xffffffffu, m, o));
    float e = expf(s - m);
    float sum = e;
    #pragma unroll
    for (int o = 16; o > 0; o >>= 1) sum += __shfl_xor_sync(0xffffffffu, sum, o);
    g_attn[bh * (HD * HD) + tid] = e / sum;
}

// ---------------- attn @ v -> fp16 operand [n][256], HFMA2 dot, 2 px/thread ----------------
__global__ __launch_bounds__(256) void av_fp16_kernel(
    const __nv_bfloat16* __restrict__ qkv2, __half* __restrict__ xh)
{
    __shared__ uint32_t A2[HD][16];   // half2 pairs (A[i][2j2], A[i][2j2+1])
    int h = blockIdx.y, b = blockIdx.z;
    int bh = b * NHEADS + h;
    int tid = threadIdx.x;
    {
        float4 f4 = *(const float4*)(g_attn + bh * 1024 + tid * 4);
        int i = (tid * 4) >> 5;
        int j2 = ((tid * 4) & 31) >> 1;
        A2[i][j2]     = packh2(f4.x, f4.y);
        A2[i][j2 + 1] = packh2(f4.z, f4.w);
    }
    __syncthreads();
    int n0 = blockIdx.x * 512 + tid * 2;
    uint32_t vf0[16], vf1[16];
    #pragma unroll
    for (int j2 = 0; j2 < 16; j2++) {
        __nv_bfloat162 va = *(const __nv_bfloat162*)(
            qkv2 + ((size_t)b * CH3 + 2 * Cdim + h * HD + 2 * j2) * Np + n0);
        __nv_bfloat162 vb = *(const __nv_bfloat162*)(
            qkv2 + ((size_t)b * CH3 + 2 * Cdim + h * HD + 2 * j2 + 1) * Np + n0);
        float2 fa = __bfloat1622float2(va), fb = __bfloat1622float2(vb);
        vf0[j2] = packh2(fa.x, fb.x);
        vf1[j2] = packh2(fa.y, fb.y);
    }
    size_t ob = ((size_t)b * Np + n0) * Cdim + h * HD;
    #pragma unroll
    for (int q = 0; q < 4; q++) {
        uint4 pk0, pk1;
        uint32_t* p0 = (uint32_t*)&pk0;
        uint32_t* p1 = (uint32_t*)&pk1;
        #pragma unroll
        for (int u = 0; u < 4; u++) {
            float s0a, s0b, s1a, s1b;
            #pragma unroll
            for (int e = 0; e < 2; e++) {
                int i = q * 8 + u * 2 + e;
                __half2 a0 = __float2half2_rn(0.f), a1 = __float2half2_rn(0.f);
                #pragma unroll
                for (int j2 = 0; j2 < 16; j2++) {
                    __half2 A = *(__half2*)&A2[i][j2];
                    a0 = __hfma2(A, *(__half2*)&vf0[j2], a0);
                    a1 = __hfma2(A, *(__half2*)&vf1[j2], a1);
                }
                float2 f0 = __half22float2(a0), f1 = __half22float2(a1);
                if (e == 0) { s0a = (f0.x + f0.y) * SC_AV; s1a = (f1.x + f1.y) * SC_AV; }
                else        { s0b = (f0.x + f0.y) * SC_AV; s1b = (f1.x + f1.y) * SC_AV; }
            }
            p0[u] = packh2(s0a, s0b);
            p1[u] = packh2(s1a, s1b);
        }
        *(uint4*)(xh + ob + q * 8)        = pk0;
        *(uint4*)(xh + ob + Cdim + q * 8) = pk1;
    }
}

// ---------------- tiled depthwise 3x3 + GELU gating -> fp16 [c][n] (x SC_GATE) ----------------
#define GATE_SMEM (2*66*128*2)   // 33792 B
__global__ __launch_bounds__(256) void dwgate2_kernel(
    const float* __restrict__ w, const float* __restrict__ bias)
{
    extern __shared__ __nv_bfloat16 ts[];
    __nv_bfloat16* t1 = ts;               // 66*128
    __nv_bfloat16* t2 = ts + 66 * 128;
    int blk = blockIdx.x;
    int half = blk & 1;
    int c = (blk >> 1) % HID;
    int b = blk / (2 * HID);
    int h0 = half * 64;
    int tid = threadIdx.x;

    const uint4* s1 = (const uint4*)(g_pin + ((size_t)b * HID2 + c) * Np);
    const uint4* s2 = (const uint4*)(g_pin + ((size_t)b * HID2 + c + HID) * Np);
    uint4* t14 = (uint4*)t1;
    uint4* t24 = (uint4*)t2;
    const uint4 z4 = make_uint4(0u, 0u, 0u, 0u);
    for (int i = tid; i < 66 * 16; i += 256) {
        int r = i >> 4, q = i & 15;
        int grow = h0 - 1 + r;
        bool ok = (grow >= 0) && (grow < Hh);
        t14[i] = ok ? s1[grow * 16 + q] : z4;
        t24[i] = ok ? s2[grow * 16 + q] : z4;
    }
    __syncthreads();

    float a00 = w[c*9+0], a01 = w[c*9+1], a02 = w[c*9+2];
    float a10 = w[c*9+3], a11 = w[c*9+4], a12 = w[c*9+5];
    float a20 = w[c*9+6], a21 = w[c*9+7], a22 = w[c*9+8];
    int c2 = c + HID;
    float b00 = w[c2*9+0], b01 = w[c2*9+1], b02 = w[c2*9+2];
    float b10 = w[c2*9+3], b11 = w[c2*9+4], b12 = w[c2*9+5];
    float b20 = w[c2*9+6], b21 = w[c2*9+7], b22 = w[c2*9+8];
    float ba = bias[c], bg = bias[c2];

    __half* op = g_gate + ((size_t)b * KPAD_G + c) * Np + h0 * Wd;
    #pragma unroll
    for (int it = 0; it < 4; it++) {
        int base = it * 2048 + tid * 8;
        int h = base >> 7, x0 = base & 127;
        float p0[10], p1[10], p2[10];
        float q0[10], q1[10], q2[10];
        load_row10(p0, t1, h,     x0, true);
        load_row10(p1, t1, h + 1, x0, true);
        load_row10(p2, t1, h + 2, x0, true);
        load_row10(q0, t2, h,     x0, true);
        load_row10(q1, t2, h + 1, x0, true);
        load_row10(q2, t2, h + 2, x0, true);
        float o[8];
        #pragma unroll
        for (int i = 0; i < 8; i++) {
            float a = ba, g = bg;
            a += a00 * p0[i] + a01 * p0[i+1] + a02 * p0[i+2];
            a += a10 * p1[i] + a11 * p1[i+1] + a12 * p1[i+2];
            a += a20 * p2[i] + a21 * p2[i+1] + a22 * p2[i+2];
            g += b00 * q0[i] + b01 * q0[i+1] + b02 * q0[i+2];
            g += b10 * q1[i] + b11 * q1[i+1] + b12 * q1[i+2];
            g += b20 * q2[i] + b21 * q2[i+1] + b22 * q2[i+2];
            float gelu = 0.5f * g * (1.f + erff(g * 0.70710678118654752f));
            o[i] = a * gelu * SC_GATE;
        }
        uint4 pk;
        pk.x = packh2(o[0], o[1]);
        pk.y = packh2(o[2], o[3]);
        pk.z = packh2(o[4], o[5]);
        pk.w = packh2(o[6], o[7]);
        *(uint4*)(op + base) = pk;
    }
}

// ---------------- launcher ----------------
extern "C" void kernel_launch(void* const* d_in, const int* in_sizes, int n_in,
                              void* d_out, int out_size)
{
    const float* x        = (const float*)d_in[0];
    const float* n1_w     = (const float*)d_in[1];
    const float* n1_b     = (const float*)d_in[2];
    const float* temp     = (const float*)d_in[3];
    const float* qkv_w    = (const float*)d_in[4];
    const float* qkv_b    = (const float*)d_in[5];
    const float* qkv_dw_w = (const float*)d_in[6];
    const float* qkv_dw_b = (const float*)d_in[7];
    const float* po_w     = (const float*)d_in[8];
    const float* po_b     = (const float*)d_in[9];
    const float* n2_w     = (const float*)d_in[10];
    const float* n2_b     = (const float*)d_in[11];
    const float* pin_w    = (const float*)d_in[12];
    const float* pin_b    = (const float*)d_in[13];
    const float* dw_w     = (const float*)d_in[14];
    const float* dw_b     = (const float*)d_in[15];
    const float* pout_w   = (const float*)d_in[16];
    const float* pout_b   = (const float*)d_in[17];
    float* out = (float*)d_out;

    float *p_x1;
    __nv_bfloat16 *p_qkv, *p_qkv2, *p_pin;
    __half *p_xh, *p_wh, *p_gate;
    cudaGetSymbolAddress((void**)&p_qkv,  g_qkv);
    cudaGetSymbolAddress((void**)&p_qkv2, g_qkv2);
    cudaGetSymbolAddress((void**)&p_x1,   g_x1);
    cudaGetSymbolAddress((void**)&p_pin,  g_pin);
    cudaGetSymbolAddress((void**)&p_gate, g_gate);
    cudaGetSymbolAddress((void**)&p_xh,   g_xh);
    cudaGetSymbolAddress((void**)&p_wh,   g_wh);

    cudaFuncSetAttribute((const void*)gemm_mma_kernel<true,  true>,  cudaFuncAttributeMaxDynamicSharedMemorySize, GEMM_SMEM);
    cudaFuncSetAttribute((const void*)gemm_mma_kernel<false, false>, cudaFuncAttributeMaxDynamicSharedMemorySize, GEMM_SMEM);
    cudaFuncSetAttribute((const void*)gemm_mma_kernel<false, true>,  cudaFuncAttributeMaxDynamicSharedMemorySize, GEMM_SMEM);
    cudaFuncSetAttribute(dwnorm_kernel,  cudaFuncAttributeMaxDynamicSharedMemorySize, DWN_SMEM);
    cudaFuncSetAttribute(dwgate2_kernel, cudaFuncAttributeMaxDynamicSharedMemorySize, GATE_SMEM);

    const float ISC_ONE  = 1.f;
    const float ISC_PO   = 1.f / SC_AV;
    const float ISC_POUT = 1.f / SC_GATE;

    // 0) weight conversion + gate pad zeroing
    wconv_all_kernel<<<(WTOT + 255) / 256, 256>>>(qkv_w, po_w, pin_w, pout_w, p_wh);
    gatepad_kernel<<<(Bsz * (KPAD_G - HID) * Np / 8 + 255) / 256, 256>>>();

    // 1) LN1 -> fp16 [c][n]
    ln_fp16_kernel<<<dim3(Np/32, Bsz), 256>>>(x, n1_w, n1_b, p_xh);
    // 2) qkv GEMM (B-trans, M=768, K=256) -> bf16
    gemm_mma_kernel<true, true><<<dim3(Np/256, 6, Bsz), 256, 3*STAGE_T>>>(
        p_wh + WOFF_QKV, p_xh, qkv_b, nullptr, p_qkv, CH3, 256, ISC_ONE);
    // 3) depthwise 3x3 on qkv (fp32 tiles, 2 blocks/channel), partial q/k norms
    dwnorm_kernel<<<Bsz*CH3*2, 256, DWN_SMEM>>>(p_qkv, qkv_dw_w, qkv_dw_b, p_qkv2);
    // 4) split-K partial S
    spart_kernel<<<dim3(SPLITS, NHEADS, Bsz), 256>>>(p_qkv2);
    // 5) reduce + norms + softmax
    attn_reduce_kernel<<<Bsz*NHEADS, 1024>>>(temp);
    // 6) attn @ v -> fp16 operand [n][256] (HFMA2)
    av_fp16_kernel<<<dim3(Np/512, NHEADS, Bsz), 256>>>(p_qkv2, p_xh);
    // 7) po GEMM (non-trans) + residual -> x1 (fp32)
    gemm_mma_kernel<false, false><<<dim3(Np/256, 2, Bsz), 256, 3*STAGE_NT>>>(
        p_wh + WOFF_PO, p_xh, po_b, x, p_x1, Cdim, 256, ISC_PO);
    // 8) LN2 -> fp16 [c][n]
    ln_fp16_kernel<<<dim3(Np/32, Bsz), 256>>>(p_x1, n2_w, n2_b, p_xh);
    // 9) FFN project-in (B-trans, M=1360 pad 1408) -> bf16
    gemm_mma_kernel<true, true><<<dim3(Np/256, MPAD_PIN/128, Bsz), 256, 3*STAGE_T>>>(
        p_wh + WOFF_PIN, p_xh, pin_b, nullptr, p_pin, HID2, 256, ISC_ONE);
    // 10) tiled depthwise + GELU gate -> fp16 [c][n] (x SC_GATE)
    dwgate2_kernel<<<Bsz*HID*2, 256, GATE_SMEM>>>(dw_w, dw_b);
    // 11) pout GEMM (B-trans, K=704) + residual -> out (fp32)
    gemm_mma_kernel<false, true><<<dim3(Np/256, 2, Bsz), 256, 3*STAGE_T>>>(
        p_wh + WOFF_POUT, p_gate, pout_b, p_x1, out, Cdim, KPAD_G, ISC_POUT);
}

// round 17
// speedup vs baseline: 1.0572x; 1.0572x over previous
#include <cuda_runtime.h>
#include <cuda_bf16.h>
#include <cuda_fp16.h>
#include <math.h>
#include <stdint.h>

// ---------------- problem constants ----------------
#define Bsz    4
#define Cdim   256
#define Hh     128
#define Wd     128
#define Np     (Hh*Wd)        // 16384
#define CH3    (3*Cdim)       // 768
#define HID    680
#define HID2   1360
#define NHEADS 8
#define HD     32
#define SPLITS 128
#define CHUNK  (Np/SPLITS)    // 128

#define KPAD_G 704
#define MPAD_PIN 1408

// static power-of-2 scales for fp16 range safety (exactly inverted in epilogue)
#define SC_AV   16.f
#define SC_GATE 512.f

// ---------------- scratch (device globals; no runtime alloc) ----------------
__device__ __align__(16) __nv_bfloat16 g_qkv [(size_t)Bsz*CH3 *Np];
__device__ __align__(16) __nv_bfloat16 g_qkv2[(size_t)Bsz*CH3 *Np];
__device__ float g_inv  [2*Bsz*Cdim];
__device__ float g_spart[(size_t)Bsz*NHEADS*SPLITS*HD*HD];
__device__ float g_attn [Bsz*NHEADS*HD*HD];
__device__ float g_x1   [(size_t)Bsz*Cdim*Np];
__device__ __align__(16) __nv_bfloat16 g_pin [(size_t)Bsz*HID2*Np];
__device__ __align__(16) __half g_gate[(size_t)Bsz*KPAD_G*Np];   // fp16, [b][c(pad 704)][n], x SC_GATE

// fp16 operand buffer (X): [c][n] for LN outputs, [n][256] for av output
__device__ __align__(16) __half g_xh[(size_t)Bsz*Np*KPAD_G];
// weights: qkv(768*256) | po(256*256) | pin(1408*256) | pout(256*704)
#define WOFF_QKV  0
#define WOFF_PO   (768*256)
#define WOFF_PIN  (WOFF_PO + 256*256)
#define WOFF_POUT (WOFF_PIN + 1408*256)
#define WTOT      (WOFF_POUT + 256*704)
__device__ __align__(16) __half g_wh[WTOT];

// ---------------- PTX helpers ----------------
__device__ __forceinline__ uint32_t smem_u32(const void* p) {
    uint32_t a;
    asm("{ .reg .u64 t; cvta.to.shared.u64 t, %1; cvt.u32.u64 %0, t; }" : "=r"(a) : "l"(p));
    return a;
}
#define CP_ASYNC16(dst, src) \
    asm volatile("cp.async.cg.shared.global [%0], [%1], 16;" :: "r"(dst), "l"(src) : "memory")
#define CP_COMMIT() asm volatile("cp.async.commit_group;" ::: "memory")
#define CP_WAIT(n)  asm volatile("cp.async.wait_group %0;" :: "n"(n) : "memory")

__device__ __forceinline__ void ldsm4(uint32_t* r, uint32_t addr) {
    asm volatile("ldmatrix.sync.aligned.m8n8.x4.shared.b16 {%0,%1,%2,%3}, [%4];"
                 : "=r"(r[0]), "=r"(r[1]), "=r"(r[2]), "=r"(r[3]) : "r"(addr));
}
__device__ __forceinline__ void ldsm4t(uint32_t* r, uint32_t addr) {
    asm volatile("ldmatrix.sync.aligned.m8n8.x4.trans.shared.b16 {%0,%1,%2,%3}, [%4];"
                 : "=r"(r[0]), "=r"(r[1]), "=r"(r[2]), "=r"(r[3]) : "r"(addr));
}
// fp16 MMA with fp16 accumulators (2 packed regs)
__device__ __forceinline__ void mma16816h(uint32_t* c, const uint32_t* a, const uint32_t* b) {
    asm volatile(
        "mma.sync.aligned.m16n8k16.row.col.f16.f16.f16.f16 "
        "{%0,%1}, {%2,%3,%4,%5}, {%6,%7}, {%0,%1};"
        : "+r"(c[0]), "+r"(c[1])
        : "r"(a[0]), "r"(a[1]), "r"(a[2]), "r"(a[3]), "r"(b[0]), "r"(b[1]));
}
__device__ __forceinline__ uint32_t packbf2(float a, float b) {
    __nv_bfloat162 h = __floats2bfloat162_rn(a, b);
    return *(uint32_t*)&h;
}
__device__ __forceinline__ uint32_t packh2(float a, float b) {
    __half2 h = __floats2half2_rn(a, b);
    return *(uint32_t*)&h;
}
__device__ __forceinline__ void unpack8(const uint4 v, float* r) {
    float2 f;
    f = __bfloat1622float2(*(const __nv_bfloat162*)&v.x); r[0] = f.x; r[1] = f.y;
    f = __bfloat1622float2(*(const __nv_bfloat162*)&v.y); r[2] = f.x; r[3] = f.y;
    f = __bfloat1622float2(*(const __nv_bfloat162*)&v.z); r[4] = f.x; r[5] = f.y;
    f = __bfloat1622float2(*(const __nv_bfloat162*)&v.w); r[6] = f.x; r[7] = f.y;
}
__device__ __forceinline__ void load_row10(float* r, const __nv_bfloat16* t,
                                           int row, int x0, bool valid) {
    if (!valid) {
        #pragma unroll
        for (int i = 0; i < 10; i++) r[i] = 0.f;
        return;
    }
    const __nv_bfloat16* p = t + row * 128;
    uint4 v = *(const uint4*)(p + x0);
    unpack8(v, r + 1);
    r[0] = (x0 > 0)   ? __bfloat162float(p[x0 - 1]) : 0.f;
    r[9] = (x0 < 120) ? __bfloat162float(p[x0 + 8]) : 0.f;
}

// ================= mma.sync GEMM fp16/fp16-accum, 128x256 block, warp tile 64x64 =================
#define TARR_B    10240          // W tile: 128 rows x 80 B
#define XT_ROW    528            // trans X row: 512 B + 16 pad
#define XNT_ROW   80
#define STAGE_T   (TARR_B + 32*XT_ROW)    // 27136
#define STAGE_NT  (TARR_B + 256*XNT_ROW)  // 30720
#define GEMM_SMEM (3*STAGE_NT)            // 92160

template<bool B_TRANS>
__device__ __forceinline__ void gemm_issue_tile(
    uint32_t st, int tid, const __half* Wh, const __half* Xh_b,
    int rowBase, int Kpad, int k0)
{
    #pragma unroll
    for (int c = tid; c < 512; c += 256) {      // W: 128 rows x 64 B
        int r = c >> 2, cc = c & 3;
        CP_ASYNC16(st + r * 80 + cc * 16,
                   Wh + (size_t)(rowBase + r) * Kpad + k0 + cc * 8);
    }
    if (B_TRANS) {
        #pragma unroll
        for (int c = tid; c < 1024; c += 256) { // X: 32 k-rows x 512 B
            int r = c >> 5, cc = c & 31;
            CP_ASYNC16(st + TARR_B + r * XT_ROW + cc * 16,
                       Xh_b + (size_t)(k0 + r) * Np + cc * 8);
        }
    } else {
        #pragma unroll
        for (int c = tid; c < 1024; c += 256) { // X: 256 n-rows x 64 B
            int r = c >> 2, cc = c & 3;
            CP_ASYNC16(st + TARR_B + r * XNT_ROW + cc * 16,
                       Xh_b + (size_t)r * Kpad + k0 + cc * 8);
        }
    }
    CP_COMMIT();
}

template<bool OUT_BF16, bool B_TRANS>
__global__ __launch_bounds__(256) void gemm_mma_kernel(
    const __half* __restrict__ Wh,
    const __half* __restrict__ Xh,
    const float* __restrict__ bias, const float* __restrict__ res,
    void* __restrict__ outp, int M, int Kpad, float isc)
{
    extern __shared__ char smem[];
    const uint32_t sb = smem_u32(smem);
    const int tid = threadIdx.x, lane = tid & 31, wid = tid >> 5;
    const int warpM = wid & 1, warpN = wid >> 1;
    const int rowBase = blockIdx.y * 128, colBase = blockIdx.x * 256, b = blockIdx.z;
    const uint32_t stageB = B_TRANS ? STAGE_T : STAGE_NT;

    const __half* Xh_b = B_TRANS
        ? (Xh + (size_t)b * Kpad * Np + colBase)
        : (Xh + ((size_t)b * Np + colBase) * Kpad);

    uint32_t acc[4][8][2];
    #pragma unroll
    for (int i = 0; i < 4; i++)
        #pragma unroll
        for (int j = 0; j < 8; j++) { acc[i][j][0] = 0u; acc[i][j][1] = 0u; }

    const int nk = Kpad >> 5;
    gemm_issue_tile<B_TRANS>(sb,          tid, Wh, Xh_b, rowBase, Kpad, 0);
    gemm_issue_tile<B_TRANS>(sb + stageB, tid, Wh, Xh_b, rowBase, Kpad, 32);

    for (int i = 0; i < nk; i++) {
        if (i + 1 < nk) CP_WAIT(1); else CP_WAIT(0);
        __syncthreads();
        if (i + 2 < nk)
            gemm_issue_tile<B_TRANS>(sb + ((i + 2) % 3) * stageB, tid, Wh, Xh_b,
                                     rowBase, Kpad, (i + 2) << 5);

        const uint32_t st = sb + (i % 3) * stageB;
        #pragma unroll
        for (int kk = 0; kk < 2; kk++) {
            uint32_t aA[4][4], bB[8][2];
            const int arow = lane & 15, ahalf = lane >> 4;
            #pragma unroll
            for (int mf = 0; mf < 4; mf++) {
                uint32_t ad = st + (uint32_t)(warpM * 64 + mf * 16 + arow) * 80
                              + kk * 32 + ahalf * 16;
                ldsm4(aA[mf], ad);
            }
            if (B_TRANS) {
                #pragma unroll
                for (int g2 = 0; g2 < 4; g2++) {
                    int kl = lane & 15;
                    int noff = warpN * 64 + g2 * 16 + ((lane & 16) ? 8 : 0);
                    uint32_t bd = st + TARR_B + (uint32_t)(kk * 16 + kl) * XT_ROW + noff * 2;
                    uint32_t t[4];
                    ldsm4t(t, bd);
                    bB[g2*2][0] = t[0]; bB[g2*2][1] = t[1];
                    bB[g2*2+1][0] = t[2]; bB[g2*2+1][1] = t[3];
                }
            } else {
                #pragma unroll
                for (int nfp = 0; nfp < 4; nfp++) {
                    int nrow = warpN * 64 + nfp * 16 + ((lane >> 4) * 8 + (lane & 7));
                    int kb = (lane >> 3) & 1;
                    uint32_t bd = st + TARR_B + (uint32_t)nrow * XNT_ROW + kk * 32 + kb * 16;
                    uint32_t t[4];
                    ldsm4(t, bd);
                    bB[nfp*2][0] = t[0]; bB[nfp*2][1] = t[1];
                    bB[nfp*2+1][0] = t[2]; bB[nfp*2+1][1] = t[3];
                }
            }
            #pragma unroll
            for (int mf = 0; mf < 4; mf++)
                #pragma unroll
                for (int nf = 0; nf < 8; nf++)
                    mma16816h(acc[mf][nf], aA[mf], bB[nf]);
        }
    }

    #pragma unroll
    for (int mf = 0; mf < 4; mf++) {
        int r0 = rowBase + warpM * 64 + mf * 16 + (lane >> 2);
        int r1 = r0 + 8;
        #pragma unroll
        for (int nf = 0; nf < 8; nf++) {
            int c0 = colBase + warpN * 64 + nf * 8 + 2 * (lane & 3);
            float2 lo = __half22float2(*(const __half2*)&acc[mf][nf][0]);
            float2 hi = __half22float2(*(const __half2*)&acc[mf][nf][1]);
            if (r0 < M) {
                float bb = __ldg(bias + r0);
                size_t go = ((size_t)b * M + r0) * Np + c0;
                float v0 = lo.x * isc + bb, v1 = lo.y * isc + bb;
                if (OUT_BF16) {
                    *(uint32_t*)((__nv_bfloat16*)outp + go) = packbf2(v0, v1);
                } else {
                    if (res) { float2 rr = *(const float2*)(res + go); v0 += rr.x; v1 += rr.y; }
                    *(float2*)((float*)outp + go) = make_float2(v0, v1);
                }
            }
            if (r1 < M) {
                float bb = __ldg(bias + r1);
                size_t go = ((size_t)b * M + r1) * Np + c0;
                float v0 = hi.x * isc + bb, v1 = hi.y * isc + bb;
                if (OUT_BF16) {
                    *(uint32_t*)((__nv_bfloat16*)outp + go) = packbf2(v0, v1);
                } else {
                    if (res) { float2 rr = *(const float2*)(res + go); v0 += rr.x; v1 += rr.y; }
                    *(float2*)((float*)outp + go) = make_float2(v0, v1);
                }
            }
        }
    }
}

// ---------------- single-pass LayerNorm -> fp16 [c][n] (coalesced) ----------------
__global__ __launch_bounds__(256) void ln_fp16_kernel(
    const float* __restrict__ in, const float* __restrict__ w,
    const float* __restrict__ bs, __half* __restrict__ xc)
{
    __shared__ float red_s[8][33];
    __shared__ float red_q[8][33];
    __shared__ float s_mu[32], s_rs[32];
    int b = blockIdx.y;
    int n0 = blockIdx.x * 32;
    int wci = threadIdx.x >> 5, lane = threadIdx.x & 31;
    int n = n0 + lane;
    const float* p = in + (size_t)b * Cdim * Np + (size_t)(wci * 32) * Np + n;
    float v[32];
    float s = 0.f, q = 0.f;
    #pragma unroll
    for (int j = 0; j < 32; j++) {
        v[j] = p[(size_t)j * Np];
        s += v[j]; q += v[j] * v[j];
    }
    red_s[wci][lane] = s;
    red_q[wci][lane] = q;
    __syncthreads();
    if (threadIdx.x < 32) {
        float ts = 0.f, tq = 0.f;
        #pragma unroll
        for (int k2 = 0; k2 < 8; k2++) { ts += red_s[k2][threadIdx.x]; tq += red_q[k2][threadIdx.x]; }
        float mu = ts * (1.f / Cdim);
        float var = fmaxf(tq * (1.f / Cdim) - mu * mu, 0.f);
        s_mu[threadIdx.x] = mu;
        s_rs[threadIdx.x] = rsqrtf(var + 1e-5f);
    }
    __syncthreads();
    float mu = s_mu[lane], rs = s_rs[lane];
    int c0 = wci * 32;
    __half* o = xc + ((size_t)b * Cdim + c0) * Np + n;
    #pragma unroll
    for (int j = 0; j < 32; j++) {
        float y = (v[j] - mu) * rs * __ldg(w + c0 + j) + __ldg(bs + c0 + j);
        o[(size_t)j * Np] = __float2half(y);
    }
}

// ---------------- zero the 24 pad channels of g_gate ----------------
__global__ void gatepad_kernel()
{
    size_t idx = (size_t)blockIdx.x * 256 + threadIdx.x;
    size_t per_b = (size_t)(KPAD_G - HID) * Np / 8;
    int b = (int)(idx / per_b);
    size_t l = (idx % per_b) * 8;
    *(uint4*)(g_gate + (size_t)b * KPAD_G * Np + (size_t)HID * Np + l) =
        make_uint4(0u, 0u, 0u, 0u);
}

// ---------------- combined weight fp16 convert ----------------
__global__ void wconv_all_kernel(
    const float* __restrict__ qkv_w, const float* __restrict__ po_w,
    const float* __restrict__ pin_w, const float* __restrict__ pout_w,
    __half* __restrict__ wh)
{
    int idx = blockIdx.x * 256 + threadIdx.x;
    if (idx >= WTOT) return;
    float v;
    if (idx < WOFF_PO) {
        v = qkv_w[idx];
    } else if (idx < WOFF_PIN) {
        v = po_w[idx - WOFF_PO];
    } else if (idx < WOFF_POUT) {
        int l = idx - WOFF_PIN;              // [1408][256]
        v = (l < 1360 * 256) ? pin_w[l] : 0.f;
    } else {
        int l = idx - WOFF_POUT;             // [256][704]
        int r = l / 704, k = l % 704;
        v = (k < 680) ? pout_w[r * 680 + k] : 0.f;
    }
    wh[idx] = __float2half(v);
}

// ---------------- fused depthwise 3x3 + q/k L2-norm, vectorized 8px/thread (R15 version) ----------------
__global__ __launch_bounds__(256) void dwnorm_kernel(
    const __nv_bfloat16* __restrict__ in, const float* __restrict__ w,
    const float* __restrict__ bias, __nv_bfloat16* __restrict__ out,
    float* __restrict__ inv)
{
    extern __shared__ __nv_bfloat16 t[];   // Np bf16 = 32KB
    int bc = blockIdx.x;
    int c = bc % CH3, b = bc / CH3;
    const int tid = threadIdx.x;
    const uint4* ip4 = (const uint4*)(in + ((size_t)b * CH3 + c) * Np);
    uint4* t4 = (uint4*)t;
    #pragma unroll
    for (int i = 0; i < 8; i++)
        t4[i * 256 + tid] = ip4[i * 256 + tid];
    __syncthreads();

    float w00 = w[c*9+0], w01 = w[c*9+1], w02 = w[c*9+2];
    float w10 = w[c*9+3], w11 = w[c*9+4], w12 = w[c*9+5];
    float w20 = w[c*9+6], w21 = w[c*9+7], w22 = w[c*9+8];
    float bb = bias[c];
    __nv_bfloat16* op = out + ((size_t)b * CH3 + c) * Np;
    float ss = 0.f;

    #pragma unroll
    for (int it = 0; it < 8; it++) {
        int base = it * 2048 + tid * 8;
        int h = base >> 7, x0 = base & 127;
        float r0[10], r1[10], r2[10];
        load_row10(r0, t, h - 1, x0, h > 0);
        load_row10(r1, t, h,     x0, true);
        load_row10(r2, t, h + 1, x0, h < 127);
        float o[8];
        #pragma unroll
        for (int i = 0; i < 8; i++) {
            float acc = bb;
            acc += w00 * r0[i] + w01 * r0[i+1] + w02 * r0[i+2];
            acc += w10 * r1[i] + w11 * r1[i+1] + w12 * r1[i+2];
            acc += w20 * r2[i] + w21 * r2[i+1] + w22 * r2[i+2];
            o[i] = acc;
            ss += acc * acc;
        }
        uint4 pk;
        pk.x = packbf2(o[0], o[1]);
        pk.y = packbf2(o[2], o[3]);
        pk.z = packbf2(o[4], o[5]);
        pk.w = packbf2(o[6], o[7]);
        *(uint4*)(op + base) = pk;
    }

    if (c < 2 * Cdim) {
        #pragma unroll
        for (int o2 = 16; o2 > 0; o2 >>= 1) ss += __shfl_xor_sync(0xffffffffu, ss, o2);
        __shared__ float red[8];
        int wid = tid >> 5;
        if ((tid & 31) == 0) red[wid] = ss;
        __syncthreads();
        if (tid == 0) {
            float s = 0.f;
            #pragma unroll
            for (int i = 0; i < 8; i++) s += red[i];
            int which = c >> 8, cc = c & 255;
            inv[which * (Bsz * Cdim) + b * Cdim + cc] = 1.f / fmaxf(sqrtf(s), 1e-12f);
        }
    }
}

// ---------------- split-K partial S, 4x4 register tiles, vectorized smem ----------------
__global__ __launch_bounds__(256) void spart_kernel(const __nv_bfloat16* __restrict__ qkv2)
{
    __shared__ float qs[CHUNK][36];
    __shared__ float ks[CHUNK][36];
    int split = blockIdx.x, h = blockIdx.y, b = blockIdx.z;
    int n0 = split * CHUNK;
    int tid = threadIdx.x;
    for (int idx = tid; idx < HD * CHUNK; idx += 256) {
        int i = idx >> 7, nn = idx & 127;
        qs[nn][i] = __bfloat162float(qkv2[((size_t)b * CH3 + h * HD + i) * Np + n0 + nn]);
        ks[nn][i] = __bfloat162float(qkv2[((size_t)b * CH3 + Cdim + h * HD + i) * Np + n0 + nn]);
    }
    __syncthreads();

    const int g  = tid >> 6;
    const int i0 = (tid >> 3) & 7;
    const int j0 = tid & 7;
    float acc[4][4];
    #pragma unroll
    for (int a = 0; a < 4; a++)
        #pragma unroll
        for (int c2 = 0; c2 < 4; c2++) acc[a][c2] = 0.f;

    #pragma unroll 4
    for (int nn = g * 32; nn < g * 32 + 32; nn++) {
        float4 qv = *(const float4*)&qs[nn][i0 * 4];
        float4 kv = *(const float4*)&ks[nn][j0 * 4];
        acc[0][0] += qv.x*kv.x; acc[0][1] += qv.x*kv.y; acc[0][2] += qv.x*kv.z; acc[0][3] += qv.x*kv.w;
        acc[1][0] += qv.y*kv.x; acc[1][1] += qv.y*kv.y; acc[1][2] += qv.y*kv.z; acc[1][3] += qv.y*kv.w;
        acc[2][0] += qv.z*kv.x; acc[2][1] += qv.z*kv.y; acc[2][2] += qv.z*kv.z; acc[2][3] += qv.z*kv.w;
        acc[3][0] += qv.w*kv.x; acc[3][1] += qv.w*kv.y; acc[3][2] += qv.w*kv.z; acc[3][3] += qv.w*kv.w;
    }
    __syncthreads();
    float* red = &qs[0][0];
    #pragma unroll
    for (int x = 0; x < 16; x++) red[tid * 17 + x] = acc[x >> 2][x & 3];
    __syncthreads();
    if (tid < 64) {
        size_t base = (((size_t)(b * NHEADS + h)) * SPLITS + split) * (HD * HD);
        #pragma unroll
        for (int x = 0; x < 16; x++) {
            float s = red[tid * 17 + x] + red[(tid + 64) * 17 + x]
                    + red[(tid + 128) * 17 + x] + red[(tid + 192) * 17 + x];
            int i = i0 * 4 + (x >> 2), j = j0 * 4 + (x & 3);
            g_spart[base + i * HD + j] = s;
        }
    }
}

// ---------------- reduce partials + softmax ----------------
__global__ __launch_bounds__(1024) void attn_reduce_kernel(
    const float* __restrict__ inv, const float* __restrict__ temp)
{
    int bh = blockIdx.x;
    int b = bh / NHEADS, h = bh % NHEADS;
    int tid = threadIdx.x;
    int i = tid >> 5, j = tid & 31;
    const float* p = g_spart + (size_t)bh * SPLITS * (HD * HD) + tid;
    float s = 0.f;
    #pragma unroll 4
    for (int sp = 0; sp < SPLITS; sp++) s += p[(size_t)sp * (HD * HD)];
    s *= inv[b * Cdim + h * HD + i] * inv[Bsz * Cdim + b * Cdim + h * HD + j] * temp[h];
    float m = s;
    #pragma unroll
    for (int o = 16; o > 0; o >>= 1) m = fmaxf(m, __shfl_xor_sync(0xffffffffu, m, o));
    float e = expf(s - m);
    float sum = e;
    #pragma unroll
    for (int o = 16; o > 0; o >>= 1) sum += __shfl_xor_sync(0xffffffffu, sum, o);
    g_attn[bh * (HD * HD) + tid] = e / sum;
}

// ---------------- attn @ v -> fp16 operand [n][256], HFMA2 dot, 2 px/thread ----------------
__global__ __launch_bounds__(256) void av_fp16_kernel(
    const __nv_bfloat16* __restrict__ qkv2, __half* __restrict__ xh)
{
    __shared__ uint32_t A2[HD][16];   // half2 pairs (A[i][2j2], A[i][2j2+1])
    int h = blockIdx.y, b = blockIdx.z;
    int bh = b * NHEADS + h;
    int tid = threadIdx.x;
    {
        float4 f4 = *(const float4*)(g_attn + bh * 1024 + tid * 4);
        int i = (tid * 4) >> 5;
        int j2 = ((tid * 4) & 31) >> 1;
        A2[i][j2]     = packh2(f4.x, f4.y);
        A2[i][j2 + 1] = packh2(f4.z, f4.w);
    }
    __syncthreads();
    int n0 = blockIdx.x * 512 + tid * 2;
    uint32_t vf0[16], vf1[16];
    #pragma unroll
    for (int j2 = 0; j2 < 16; j2++) {
        __nv_bfloat162 va = *(const __nv_bfloat162*)(
            qkv2 + ((size_t)b * CH3 + 2 * Cdim + h * HD + 2 * j2) * Np + n0);
        __nv_bfloat162 vb = *(const __nv_bfloat162*)(
            qkv2 + ((size_t)b * CH3 + 2 * Cdim + h * HD + 2 * j2 + 1) * Np + n0);
        float2 fa = __bfloat1622float2(va), fb = __bfloat1622float2(vb);
        vf0[j2] = packh2(fa.x, fb.x);
        vf1[j2] = packh2(fa.y, fb.y);
    }
    size_t ob = ((size_t)b * Np + n0) * Cdim + h * HD;
    #pragma unroll
    for (int q = 0; q < 4; q++) {
        uint4 pk0, pk1;
        uint32_t* p0 = (uint32_t*)&pk0;
        uint32_t* p1 = (uint32_t*)&pk1;
        #pragma unroll
        for (int u = 0; u < 4; u++) {
            float s0a, s0b, s1a, s1b;
            #pragma unroll
            for (int e = 0; e < 2; e++) {
                int i = q * 8 + u * 2 + e;
                __half2 a0 = __float2half2_rn(0.f), a1 = __float2half2_rn(0.f);
                #pragma unroll
                for (int j2 = 0; j2 < 16; j2++) {
                    __half2 A = *(__half2*)&A2[i][j2];
                    a0 = __hfma2(A, *(__half2*)&vf0[j2], a0);
                    a1 = __hfma2(A, *(__half2*)&vf1[j2], a1);
                }
                float2 f0 = __half22float2(a0), f1 = __half22float2(a1);
                if (e == 0) { s0a = (f0.x + f0.y) * SC_AV; s1a = (f1.x + f1.y) * SC_AV; }
                else        { s0b = (f0.x + f0.y) * SC_AV; s1b = (f1.x + f1.y) * SC_AV; }
            }
            p0[u] = packh2(s0a, s0b);
            p1[u] = packh2(s1a, s1b);
        }
        *(uint4*)(xh + ob + q * 8)        = pk0;
        *(uint4*)(xh + ob + Cdim + q * 8) = pk1;
    }
}

// ---------------- tiled depthwise 3x3 + GELU gating -> fp16 [c][n] (x SC_GATE) ----------------
#define GATE_SMEM (2*66*128*2)   // 33792 B
__global__ __launch_bounds__(256) void dwgate2_kernel(
    const float* __restrict__ w, const float* __restrict__ bias)
{
    extern __shared__ __nv_bfloat16 ts[];
    __nv_bfloat16* t1 = ts;               // 66*128
    __nv_bfloat16* t2 = ts + 66 * 128;
    int blk = blockIdx.x;
    int half = blk & 1;
    int c = (blk >> 1) % HID;
    int b = blk / (2 * HID);
    int h0 = half * 64;
    int tid = threadIdx.x;

    const uint4* s1 = (const uint4*)(g_pin + ((size_t)b * HID2 + c) * Np);
    const uint4* s2 = (const uint4*)(g_pin + ((size_t)b * HID2 + c + HID) * Np);
    uint4* t14 = (uint4*)t1;
    uint4* t24 = (uint4*)t2;
    const uint4 z4 = make_uint4(0u, 0u, 0u, 0u);
    for (int i = tid; i < 66 * 16; i += 256) {
        int r = i >> 4, q = i & 15;
        int grow = h0 - 1 + r;
        bool ok = (grow >= 0) && (grow < Hh);
        t14[i] = ok ? s1[grow * 16 + q] : z4;
        t24[i] = ok ? s2[grow * 16 + q] : z4;
    }
    __syncthreads();

    float a00 = w[c*9+0], a01 = w[c*9+1], a02 = w[c*9+2];
    float a10 = w[c*9+3], a11 = w[c*9+4], a12 = w[c*9+5];
    float a20 = w[c*9+6], a21 = w[c*9+7], a22 = w[c*9+8];
    int c2 = c + HID;
    float b00 = w[c2*9+0], b01 = w[c2*9+1], b02 = w[c2*9+2];
    float b10 = w[c2*9+3], b11 = w[c2*9+4], b12 = w[c2*9+5];
    float b20 = w[c2*9+6], b21 = w[c2*9+7], b22 = w[c2*9+8];
    float ba = bias[c], bg = bias[c2];

    __half* op = g_gate + ((size_t)b * KPAD_G + c) * Np + h0 * Wd;
    #pragma unroll
    for (int it = 0; it < 4; it++) {
        int base = it * 2048 + tid * 8;
        int h = base >> 7, x0 = base & 127;
        float p0[10], p1[10], p2[10];
        float q0[10], q1[10], q2[10];
        load_row10(p0, t1, h,     x0, true);
        load_row10(p1, t1, h + 1, x0, true);
        load_row10(p2, t1, h + 2, x0, true);
        load_row10(q0, t2, h,     x0, true);
        load_row10(q1, t2, h + 1, x0, true);
        load_row10(q2, t2, h + 2, x0, true);
        float o[8];
        #pragma unroll
        for (int i = 0; i < 8; i++) {
            float a = ba, g = bg;
            a += a00 * p0[i] + a01 * p0[i+1] + a02 * p0[i+2];
            a += a10 * p1[i] + a11 * p1[i+1] + a12 * p1[i+2];
            a += a20 * p2[i] + a21 * p2[i+1] + a22 * p2[i+2];
            g += b00 * q0[i] + b01 * q0[i+1] + b02 * q0[i+2];
            g += b10 * q1[i] + b11 * q1[i+1] + b12 * q1[i+2];
            g += b20 * q2[i] + b21 * q2[i+1] + b22 * q2[i+2];
            float gelu = 0.5f * g * (1.f + erff(g * 0.70710678118654752f));
            o[i] = a * gelu * SC_GATE;
        }
        uint4 pk;
        pk.x = packh2(o[0], o[1]);
        pk.y = packh2(o[2], o[3]);
        pk.z = packh2(o[4], o[5]);
        pk.w = packh2(o[6], o[7]);
        *(uint4*)(op + base) = pk;
    }
}

// ---------------- launcher ----------------
extern "C" void kernel_launch(void* const* d_in, const int* in_sizes, int n_in,
                              void* d_out, int out_size)
{
    const float* x        = (const float*)d_in[0];
    const float* n1_w     = (const float*)d_in[1];
    const float* n1_b     = (const float*)d_in[2];
    const float* temp     = (const float*)d_in[3];
    const float* qkv_w    = (const float*)d_in[4];
    const float* qkv_b    = (const float*)d_in[5];
    const float* qkv_dw_w = (const float*)d_in[6];
    const float* qkv_dw_b = (const float*)d_in[7];
    const float* po_w     = (const float*)d_in[8];
    const float* po_b     = (const float*)d_in[9];
    const float* n2_w     = (const float*)d_in[10];
    const float* n2_b     = (const float*)d_in[11];
    const float* pin_w    = (const float*)d_in[12];
    const float* pin_b    = (const float*)d_in[13];
    const float* dw_w     = (const float*)d_in[14];
    const float* dw_b     = (const float*)d_in[15];
    const float* pout_w   = (const float*)d_in[16];
    const float* pout_b   = (const float*)d_in[17];
    float* out = (float*)d_out;

    float *p_inv, *p_x1;
    __nv_bfloat16 *p_qkv, *p_qkv2, *p_pin;
    __half *p_xh, *p_wh, *p_gate;
    cudaGetSymbolAddress((void**)&p_qkv,  g_qkv);
    cudaGetSymbolAddress((void**)&p_qkv2, g_qkv2);
    cudaGetSymbolAddress((void**)&p_inv,  g_inv);
    cudaGetSymbolAddress((void**)&p_x1,   g_x1);
    cudaGetSymbolAddress((void**)&p_pin,  g_pin);
    cudaGetSymbolAddress((void**)&p_gate, g_gate);
    cudaGetSymbolAddress((void**)&p_xh,   g_xh);
    cudaGetSymbolAddress((void**)&p_wh,   g_wh);

    cudaFuncSetAttribute((const void*)gemm_mma_kernel<true,  true>,  cudaFuncAttributeMaxDynamicSharedMemorySize, GEMM_SMEM);
    cudaFuncSetAttribute((const void*)gemm_mma_kernel<false, false>, cudaFuncAttributeMaxDynamicSharedMemorySize, GEMM_SMEM);
    cudaFuncSetAttribute((const void*)gemm_mma_kernel<false, true>,  cudaFuncAttributeMaxDynamicSharedMemorySize, GEMM_SMEM);
    cudaFuncSetAttribute(dwnorm_kernel,  cudaFuncAttributeMaxDynamicSharedMemorySize, Np * 2);
    cudaFuncSetAttribute(dwgate2_kernel, cudaFuncAttributeMaxDynamicSharedMemorySize, GATE_SMEM);

    const float ISC_ONE  = 1.f;
    const float ISC_PO   = 1.f / SC_AV;
    const float ISC_POUT = 1.f / SC_GATE;

    // 0) weight conversion + gate pad zeroing
    wconv_all_kernel<<<(WTOT + 255) / 256, 256>>>(qkv_w, po_w, pin_w, pout_w, p_wh);
    gatepad_kernel<<<(Bsz * (KPAD_G - HID) * Np / 8 + 255) / 256, 256>>>();

    // 1) LN1 -> fp16 [c][n]
    ln_fp16_kernel<<<dim3(Np/32, Bsz), 256>>>(x, n1_w, n1_b, p_xh);
    // 2) qkv GEMM (B-trans, M=768, K=256) -> bf16
    gemm_mma_kernel<true, true><<<dim3(Np/256, 6, Bsz), 256, 3*STAGE_T>>>(
        p_wh + WOFF_QKV, p_xh, qkv_b, nullptr, p_qkv, CH3, 256, ISC_ONE);
    // 3) depthwise 3x3 on qkv, fused q/k norms (R15 version)
    dwnorm_kernel<<<Bsz*CH3, 256, Np*2>>>(p_qkv, qkv_dw_w, qkv_dw_b, p_qkv2, p_inv);
    // 4) split-K partial S
    spart_kernel<<<dim3(SPLITS, NHEADS, Bsz), 256>>>(p_qkv2);
    // 5) reduce + softmax
    attn_reduce_kernel<<<Bsz*NHEADS, 1024>>>(p_inv, temp);
    // 6) attn @ v -> fp16 operand [n][256] (HFMA2)
    av_fp16_kernel<<<dim3(Np/512, NHEADS, Bsz), 256>>>(p_qkv2, p_xh);
    // 7) po GEMM (non-trans) + residual -> x1 (fp32)
    gemm_mma_kernel<false, false><<<dim3(Np/256, 2, Bsz), 256, 3*STAGE_NT>>>(
        p_wh + WOFF_PO, p_xh, po_b, x, p_x1, Cdim, 256, ISC_PO);
    // 8) LN2 -> fp16 [c][n]
    ln_fp16_kernel<<<dim3(Np/32, Bsz), 256>>>(p_x1, n2_w, n2_b, p_xh);
    // 9) FFN project-in (B-trans, M=1360 pad 1408) -> bf16
    gemm_mma_kernel<true, true><<<dim3(Np/256, MPAD_PIN/128, Bsz), 256, 3*STAGE_T>>>(
        p_wh + WOFF_PIN, p_xh, pin_b, nullptr, p_pin, HID2, 256, ISC_ONE);
    // 10) tiled depthwise + GELU gate -> fp16 [c][n] (x SC_GATE)
    dwgate2_kernel<<<Bsz*HID*2, 256, GATE_SMEM>>>(dw_w, dw_b);
    // 11) pout GEMM (B-trans, K=704) + residual -> out (fp32)
    gemm_mma_kernel<false, true><<<dim3(Np/256, 2, Bsz), 256, 3*STAGE_T>>>(
        p_wh + WOFF_POUT, p_gate, pout_b, p_x1, out, Cdim, KPAD_G, ISC_POUT);
}